// round 4
// baseline (speedup 1.0000x reference)
#include <cuda_runtime.h>
#include <math.h>

#define BATCH 8
#define CCH   512      // C
#define ICH   256      // IC = C/2
#define HW    2304     // 48*48
#define BN_EPS 1e-5f

#define HEAVY_BLOCKS 296   // co-resident on 148 SMs (8/SM by threads)

// float4s per channel row and finalize geometry
#define F4_PER_CH   (HW / 4)        // 576
#define FIN_THREADS 192
#define F4_PER_THR  (F4_PER_CH / FIN_THREADS)  // 3

// ---------------------------------------------------------------------------
// Scratch (device globals). Heavy path only touched when gamma != 0 somewhere.
// ---------------------------------------------------------------------------
__device__ float d_g [BATCH * ICH * HW];
__device__ float d_th[BATCH * ICH * HW];
__device__ float d_ph[BATCH * ICH * HW];
__device__ float d_y [BATCH * ICH * HW];
__device__ float d_wy[BATCH * CCH * HW];
__device__ float d_psum  [CCH * BATCH];
__device__ float d_psumsq[CCH * BATCH];

// Replay-safe software global barrier (gen monotonic; count wraps via atomicInc).
__device__ unsigned d_bar_count = 0;
__device__ unsigned d_bar_gen   = 0;

__device__ __forceinline__ void global_barrier(unsigned nblocks) {
    __syncthreads();
    __threadfence();
    if (threadIdx.x == 0) {
        unsigned target = atomicAdd(&d_bar_gen, 0u) + 1u;
        unsigned prev = atomicInc(&d_bar_count, nblocks - 1u);
        if (prev == nblocks - 1u) {
            atomicAdd(&d_bar_gen, 1u);
        } else {
            while (atomicAdd(&d_bar_gen, 0u) < target) { }
        }
    }
    __syncthreads();
    __threadfence();
}

__device__ __forceinline__ bool gamma_all_zero_256(const float* __restrict__ gamma) {
    __shared__ int s_any;
    if (threadIdx.x == 0) s_any = 0;
    __syncthreads();
    float a = gamma[threadIdx.x];
    float b = gamma[threadIdx.x + 256];
    if (a != 0.0f || b != 0.0f) atomicOr(&s_any, 1);
    __syncthreads();
    return s_any == 0;
}

// ---------------------------------------------------------------------------
// K1: entire heavy path, one persistent kernel. Early-exit when gamma == 0.
// ---------------------------------------------------------------------------
__global__ void __launch_bounds__(256) heavy_k(
        const float* __restrict__ x,
        const float* __restrict__ g_w,  const float* __restrict__ g_b,
        const float* __restrict__ th_w, const float* __restrict__ th_b,
        const float* __restrict__ ph_w, const float* __restrict__ ph_b,
        const float* __restrict__ w_w,  const float* __restrict__ w_b,
        const float* __restrict__ gamma) {
    if (gamma_all_zero_256(gamma)) return;

    __shared__ float sh_big[HW];
    __shared__ float sh_qv[ICH];
    __shared__ float sh_red[256];

    // ---- Stage A: input convs -------------------------------------------
    {
        const int NWORK = 3 * BATCH * ICH;
        for (int item = blockIdx.x; item < NWORK; item += gridDim.x) {
            int sel = item / (BATCH * ICH);
            int rem = item % (BATCH * ICH);
            int b = rem / ICH, o = rem % ICH;
            const float* w    = (sel == 0) ? g_w : (sel == 1) ? th_w : ph_w;
            const float* bias = (sel == 0) ? g_b : (sel == 1) ? th_b : ph_b;
            float* out        = (sel == 0) ? d_g : (sel == 1) ? d_th : d_ph;
            for (int i = threadIdx.x; i < CCH; i += blockDim.x)
                sh_big[i] = w[o * CCH + i];
            __syncthreads();
            const float* xb = x + (long)b * CCH * HW;
            float bz = bias[o];
            for (int p = threadIdx.x; p < HW; p += blockDim.x) {
                float acc = bz;
                #pragma unroll 8
                for (int c = 0; c < CCH; c++) acc = fmaf(sh_big[c], xb[c * HW + p], acc);
                out[((long)b * ICH + o) * HW + p] = acc;
            }
            __syncthreads();
        }
    }
    global_barrier(HEAVY_BLOCKS);

    // ---- Stage B: attention ---------------------------------------------
    {
        const int NWORK = BATCH * HW;
        for (int bq = blockIdx.x; bq < NWORK; bq += gridDim.x) {
            int b = bq / HW, q = bq % HW;
            const float* th = d_th + (long)b * ICH * HW;
            const float* ph = d_ph + (long)b * ICH * HW;
            const float* g  = d_g  + (long)b * ICH * HW;
            for (int i = threadIdx.x; i < ICH; i += blockDim.x) sh_qv[i] = th[i * HW + q];
            __syncthreads();
            for (int k = threadIdx.x; k < HW; k += blockDim.x) {
                float acc = 0.0f;
                #pragma unroll 8
                for (int c = 0; c < ICH; c++) acc = fmaf(sh_qv[c], ph[c * HW + k], acc);
                sh_big[k] = acc;
            }
            __syncthreads();
            float m = -1e30f;
            for (int k = threadIdx.x; k < HW; k += blockDim.x) m = fmaxf(m, sh_big[k]);
            sh_red[threadIdx.x] = m;
            __syncthreads();
            for (int s = blockDim.x / 2; s > 0; s >>= 1) {
                if (threadIdx.x < s)
                    sh_red[threadIdx.x] = fmaxf(sh_red[threadIdx.x], sh_red[threadIdx.x + s]);
                __syncthreads();
            }
            m = sh_red[0];
            __syncthreads();
            float s = 0.0f;
            for (int k = threadIdx.x; k < HW; k += blockDim.x) {
                float e = __expf(sh_big[k] - m);
                sh_big[k] = e;
                s += e;
            }
            sh_red[threadIdx.x] = s;
            __syncthreads();
            for (int st = blockDim.x / 2; st > 0; st >>= 1) {
                if (threadIdx.x < st) sh_red[threadIdx.x] += sh_red[threadIdx.x + st];
                __syncthreads();
            }
            float invs = 1.0f / sh_red[0];
            __syncthreads();
            for (int c = threadIdx.x; c < ICH; c += blockDim.x) {
                const float* gr = g + (long)c * HW;
                float acc = 0.0f;
                #pragma unroll 8
                for (int k = 0; k < HW; k++) acc = fmaf(sh_big[k], gr[k], acc);
                d_y[((long)b * ICH + c) * HW + q] = acc * invs;
            }
            __syncthreads();
        }
    }
    global_barrier(HEAVY_BLOCKS);

    // ---- Stage C: output conv + BN partial sums -------------------------
    {
        const int NWORK = BATCH * CCH;
        for (int bc = blockIdx.x; bc < NWORK; bc += gridDim.x) {
            int b = bc / CCH, c = bc % CCH;
            for (int i = threadIdx.x; i < ICH; i += blockDim.x)
                sh_big[i] = w_w[c * ICH + i];
            __syncthreads();
            const float* yb = d_y + (long)b * ICH * HW;
            float bz = w_b[c];
            float ls = 0.0f, lss = 0.0f;
            for (int p = threadIdx.x; p < HW; p += blockDim.x) {
                float acc = bz;
                #pragma unroll 8
                for (int ic = 0; ic < ICH; ic++) acc = fmaf(sh_big[ic], yb[ic * HW + p], acc);
                d_wy[((long)b * CCH + c) * HW + p] = acc;
                ls += acc;
                lss += acc * acc;
            }
            sh_red[threadIdx.x] = ls;
            __syncthreads();
            for (int st = blockDim.x / 2; st > 0; st >>= 1) {
                if (threadIdx.x < st) sh_red[threadIdx.x] += sh_red[threadIdx.x + st];
                __syncthreads();
            }
            if (threadIdx.x == 0) d_psum[c * BATCH + b] = sh_red[0];
            __syncthreads();
            sh_red[threadIdx.x] = lss;
            __syncthreads();
            for (int st = blockDim.x / 2; st > 0; st >>= 1) {
                if (threadIdx.x < st) sh_red[threadIdx.x] += sh_red[threadIdx.x + st];
                __syncthreads();
            }
            if (threadIdx.x == 0) d_psumsq[c * BATCH + b] = sh_red[0];
            __syncthreads();
        }
    }
}

// ---------------------------------------------------------------------------
// K2: finalize, one block per linear channel (b*CCH + c). 4096 blocks x 192.
// Channel = exactly 576 float4s -> 3 per thread. No divisions anywhere:
// c = lc & (CCH-1). Block-uniform gamma branch; streaming loads/stores.
// ---------------------------------------------------------------------------
__global__ void __launch_bounds__(FIN_THREADS) finalize_k(
        const float* __restrict__ x,
        const float* __restrict__ gamma,
        const float* __restrict__ beta,
        float* __restrict__ out) {
    __shared__ float s_mu, s_inv, s_ga, s_be;
    const int lc = blockIdx.x;            // linear channel 0..4095
    const int c  = lc & (CCH - 1);
    if (threadIdx.x == 0) {
        float ga = gamma[c];
        float mu = 0.0f, inv = 0.0f;
        if (ga != 0.0f) {
            float s = 0.0f, ss = 0.0f;
            #pragma unroll
            for (int b = 0; b < BATCH; b++) {
                s  += d_psum  [c * BATCH + b];
                ss += d_psumsq[c * BATCH + b];
            }
            const float N = (float)(BATCH * HW);
            mu = s / N;
            float var = ss / N - mu * mu;
            inv = rsqrtf(var + BN_EPS) * ga;
        }
        s_mu = mu; s_inv = inv; s_ga = ga; s_be = beta[c];
    }
    __syncthreads();

    const float4* xp = reinterpret_cast<const float4*>(x) + (long)lc * F4_PER_CH;
    float4*       op = reinterpret_cast<float4*>(out)     + (long)lc * F4_PER_CH;
    float be = s_be;

    if (s_ga == 0.0f) {
        float4 v0 = __ldcs(&xp[threadIdx.x]);
        float4 v1 = __ldcs(&xp[threadIdx.x + FIN_THREADS]);
        float4 v2 = __ldcs(&xp[threadIdx.x + 2 * FIN_THREADS]);
        v0.x += be; v0.y += be; v0.z += be; v0.w += be;
        v1.x += be; v1.y += be; v1.z += be; v1.w += be;
        v2.x += be; v2.y += be; v2.z += be; v2.w += be;
        __stcs(&op[threadIdx.x],                   v0);
        __stcs(&op[threadIdx.x + FIN_THREADS],     v1);
        __stcs(&op[threadIdx.x + 2 * FIN_THREADS], v2);
    } else {
        const float4* wp = reinterpret_cast<const float4*>(d_wy) + (long)lc * F4_PER_CH;
        float mu = s_mu, inv = s_inv;
        #pragma unroll
        for (int k = 0; k < F4_PER_THR; k++) {
            int i = threadIdx.x + k * FIN_THREADS;
            float4 xv = __ldcs(&xp[i]);
            float4 wv = __ldcs(&wp[i]);
            float4 o;
            o.x = xv.x + (wv.x - mu) * inv + be;
            o.y = xv.y + (wv.y - mu) * inv + be;
            o.z = xv.z + (wv.z - mu) * inv + be;
            o.w = xv.w + (wv.w - mu) * inv + be;
            __stcs(&op[i], o);
        }
    }
}

// ---------------------------------------------------------------------------
// launch
// inputs: 0 x, 1 g_w, 2 g_b, 3 theta_w, 4 theta_b, 5 phi_w, 6 phi_b,
//         7 w_w, 8 w_b, 9 bn_gamma, 10 bn_beta
// ---------------------------------------------------------------------------
extern "C" void kernel_launch(void* const* d_in, const int* in_sizes, int n_in,
                              void* d_out, int out_size) {
    const float* x      = (const float*)d_in[0];
    const float* g_w    = (const float*)d_in[1];
    const float* g_b    = (const float*)d_in[2];
    const float* th_w   = (const float*)d_in[3];
    const float* th_b   = (const float*)d_in[4];
    const float* ph_w   = (const float*)d_in[5];
    const float* ph_b   = (const float*)d_in[6];
    const float* w_w    = (const float*)d_in[7];
    const float* w_b    = (const float*)d_in[8];
    const float* gamma  = (const float*)d_in[9];
    const float* beta   = (const float*)d_in[10];
    float* out          = (float*)d_out;

    heavy_k<<<HEAVY_BLOCKS, 256>>>(x, g_w, g_b, th_w, th_b, ph_w, ph_b,
                                   w_w, w_b, gamma);

    finalize_k<<<BATCH * CCH, FIN_THREADS>>>(x, gamma, beta, out);
}

// round 5
// speedup vs baseline: 1.2165x; 1.2165x over previous
#include <cuda_runtime.h>
#include <math.h>

#define BATCH 8
#define CCH   512      // C
#define ICH   256      // IC = C/2
#define HW    2304     // 48*48
#define BN_EPS 1e-5f

#define NBLK   296     // 2 blocks/SM on 148 SMs -> co-resident (barrier-safe)
#define NTHR   512
#define F4_PER_CH (HW / 4)                 // 576
#define N4_TOTAL  (BATCH * CCH * F4_PER_CH) // 2,359,296 float4s

// ---------------------------------------------------------------------------
// Scratch (device globals). Heavy path only touched when gamma != 0 somewhere.
// ---------------------------------------------------------------------------
__device__ float d_g [BATCH * ICH * HW];
__device__ float d_th[BATCH * ICH * HW];
__device__ float d_ph[BATCH * ICH * HW];
__device__ float d_y [BATCH * ICH * HW];
__device__ float d_wy[BATCH * CCH * HW];
__device__ float d_psum  [CCH * BATCH];
__device__ float d_psumsq[CCH * BATCH];
__device__ float d_mu [CCH];
__device__ float d_inv[CCH];   // gamma * rsqrt(var + eps)

// Replay-safe software global barrier (gen monotonic; count wraps via atomicInc).
__device__ unsigned d_bar_count = 0;
__device__ unsigned d_bar_gen   = 0;

__device__ __forceinline__ void global_barrier(unsigned nblocks) {
    __syncthreads();
    __threadfence();
    if (threadIdx.x == 0) {
        unsigned target = atomicAdd(&d_bar_gen, 0u) + 1u;
        unsigned prev = atomicInc(&d_bar_count, nblocks - 1u);
        if (prev == nblocks - 1u) {
            atomicAdd(&d_bar_gen, 1u);
        } else {
            while (atomicAdd(&d_bar_gen, 0u) < target) { }
        }
    }
    __syncthreads();
    __threadfence();
}

// blockDim.x == 512 == CCH: thread t checks gamma[t]. Uniform across blocks.
__device__ __forceinline__ bool gamma_all_zero(const float* __restrict__ gamma) {
    __shared__ int s_any;
    if (threadIdx.x == 0) s_any = 0;
    __syncthreads();
    if (gamma[threadIdx.x] != 0.0f) atomicOr(&s_any, 1);
    __syncthreads();
    return s_any == 0;
}

// ---------------------------------------------------------------------------
// THE kernel: everything in one launch.
// Dead path (gamma == 0): jump straight to finalize (out = x + beta[c]).
// Live path: convs -> attention -> out-conv + BN partials -> stats -> finalize.
// ---------------------------------------------------------------------------
__global__ void __launch_bounds__(NTHR, 2) fused_k(
        const float* __restrict__ x,
        const float* __restrict__ g_w,  const float* __restrict__ g_b,
        const float* __restrict__ th_w, const float* __restrict__ th_b,
        const float* __restrict__ ph_w, const float* __restrict__ ph_b,
        const float* __restrict__ w_w,  const float* __restrict__ w_b,
        const float* __restrict__ gamma,
        const float* __restrict__ beta,
        float* __restrict__ out) {

    const bool gzero = gamma_all_zero(gamma);
    const int gtid    = blockIdx.x * NTHR + threadIdx.x;
    const int gstride = NBLK * NTHR;

    if (gzero) {
        // ---- Fast finalize: out = x + beta[c] ---------------------------
        const float4* xp = reinterpret_cast<const float4*>(x);
        float4*       op = reinterpret_cast<float4*>(out);
        for (int i = gtid; i < N4_TOTAL; i += gstride) {
            int c = (i / F4_PER_CH) & (CCH - 1);
            float be = beta[c];
            float4 v = xp[i];
            v.x += be; v.y += be; v.z += be; v.w += be;
            __stcs(&op[i], v);
        }
        return;
    }

    // =====================================================================
    // Heavy path
    // =====================================================================
    __shared__ float sh_big[HW];
    __shared__ float sh_qv[ICH];
    __shared__ float sh_red[NTHR];

    // ---- Stage A: g/theta/phi 1x1 convs ---------------------------------
    {
        const int NWORK = 3 * BATCH * ICH;
        for (int item = blockIdx.x; item < NWORK; item += gridDim.x) {
            int sel = item / (BATCH * ICH);
            int rem = item % (BATCH * ICH);
            int b = rem / ICH, o = rem % ICH;
            const float* w    = (sel == 0) ? g_w : (sel == 1) ? th_w : ph_w;
            const float* bias = (sel == 0) ? g_b : (sel == 1) ? th_b : ph_b;
            float* outp       = (sel == 0) ? d_g : (sel == 1) ? d_th : d_ph;
            for (int i = threadIdx.x; i < CCH; i += NTHR)
                sh_big[i] = w[o * CCH + i];
            __syncthreads();
            const float* xb = x + (long)b * CCH * HW;
            float bz = bias[o];
            for (int p = threadIdx.x; p < HW; p += NTHR) {
                float acc = bz;
                #pragma unroll 8
                for (int c = 0; c < CCH; c++) acc = fmaf(sh_big[c], xb[c * HW + p], acc);
                outp[((long)b * ICH + o) * HW + p] = acc;
            }
            __syncthreads();
        }
    }
    global_barrier(NBLK);

    // ---- Stage B: attention ---------------------------------------------
    {
        const int NWORK = BATCH * HW;
        for (int bq = blockIdx.x; bq < NWORK; bq += gridDim.x) {
            int b = bq / HW, q = bq % HW;
            const float* th = d_th + (long)b * ICH * HW;
            const float* ph = d_ph + (long)b * ICH * HW;
            const float* g  = d_g  + (long)b * ICH * HW;
            for (int i = threadIdx.x; i < ICH; i += NTHR) sh_qv[i] = th[i * HW + q];
            __syncthreads();
            for (int k = threadIdx.x; k < HW; k += NTHR) {
                float acc = 0.0f;
                #pragma unroll 8
                for (int c = 0; c < ICH; c++) acc = fmaf(sh_qv[c], ph[c * HW + k], acc);
                sh_big[k] = acc;
            }
            __syncthreads();
            float m = -1e30f;
            for (int k = threadIdx.x; k < HW; k += NTHR) m = fmaxf(m, sh_big[k]);
            sh_red[threadIdx.x] = m;
            __syncthreads();
            for (int s = NTHR / 2; s > 0; s >>= 1) {
                if (threadIdx.x < s)
                    sh_red[threadIdx.x] = fmaxf(sh_red[threadIdx.x], sh_red[threadIdx.x + s]);
                __syncthreads();
            }
            m = sh_red[0];
            __syncthreads();
            float s = 0.0f;
            for (int k = threadIdx.x; k < HW; k += NTHR) {
                float e = __expf(sh_big[k] - m);
                sh_big[k] = e;
                s += e;
            }
            sh_red[threadIdx.x] = s;
            __syncthreads();
            for (int st = NTHR / 2; st > 0; st >>= 1) {
                if (threadIdx.x < st) sh_red[threadIdx.x] += sh_red[threadIdx.x + st];
                __syncthreads();
            }
            float invs = 1.0f / sh_red[0];
            __syncthreads();
            for (int c = threadIdx.x; c < ICH; c += NTHR) {
                const float* gr = g + (long)c * HW;
                float acc = 0.0f;
                #pragma unroll 8
                for (int k = 0; k < HW; k++) acc = fmaf(sh_big[k], gr[k], acc);
                d_y[((long)b * ICH + c) * HW + q] = acc * invs;
            }
            __syncthreads();
        }
    }
    global_barrier(NBLK);

    // ---- Stage C: output conv + per-(b,c) BN partials -------------------
    {
        const int NWORK = BATCH * CCH;
        for (int bc = blockIdx.x; bc < NWORK; bc += gridDim.x) {
            int b = bc / CCH, c = bc % CCH;
            for (int i = threadIdx.x; i < ICH; i += NTHR)
                sh_big[i] = w_w[c * ICH + i];
            __syncthreads();
            const float* yb = d_y + (long)b * ICH * HW;
            float bz = w_b[c];
            float ls = 0.0f, lss = 0.0f;
            for (int p = threadIdx.x; p < HW; p += NTHR) {
                float acc = bz;
                #pragma unroll 8
                for (int ic = 0; ic < ICH; ic++) acc = fmaf(sh_big[ic], yb[ic * HW + p], acc);
                d_wy[((long)b * CCH + c) * HW + p] = acc;
                ls += acc;
                lss += acc * acc;
            }
            sh_red[threadIdx.x] = ls;
            __syncthreads();
            for (int st = NTHR / 2; st > 0; st >>= 1) {
                if (threadIdx.x < st) sh_red[threadIdx.x] += sh_red[threadIdx.x + st];
                __syncthreads();
            }
            if (threadIdx.x == 0) d_psum[c * BATCH + b] = sh_red[0];
            __syncthreads();
            sh_red[threadIdx.x] = lss;
            __syncthreads();
            for (int st = NTHR / 2; st > 0; st >>= 1) {
                if (threadIdx.x < st) sh_red[threadIdx.x] += sh_red[threadIdx.x + st];
                __syncthreads();
            }
            if (threadIdx.x == 0) d_psumsq[c * BATCH + b] = sh_red[0];
            __syncthreads();
        }
    }
    global_barrier(NBLK);

    // ---- Stage D: per-channel mean / inv (block 0, thread t = channel t) --
    if (blockIdx.x == 0) {
        int c = threadIdx.x;   // NTHR == CCH == 512
        float s = 0.0f, ss = 0.0f;
        #pragma unroll
        for (int b = 0; b < BATCH; b++) {
            s  += d_psum  [c * BATCH + b];
            ss += d_psumsq[c * BATCH + b];
        }
        const float N = (float)(BATCH * HW);
        float mu = s / N;
        float var = ss / N - mu * mu;
        d_mu[c]  = mu;
        d_inv[c] = rsqrtf(var + BN_EPS) * gamma[c];
    }
    global_barrier(NBLK);

    // ---- Stage E: finalize with BN ---------------------------------------
    {
        const float4* xp = reinterpret_cast<const float4*>(x);
        const float4* wp = reinterpret_cast<const float4*>(d_wy);
        float4*       op = reinterpret_cast<float4*>(out);
        for (int i = gtid; i < N4_TOTAL; i += gstride) {
            int c = (i / F4_PER_CH) & (CCH - 1);
            float be  = beta[c];
            float mu  = d_mu[c];
            float inv = d_inv[c];
            float4 xv = xp[i];
            float4 wv = wp[i];
            float4 o;
            o.x = xv.x + (wv.x - mu) * inv + be;
            o.y = xv.y + (wv.y - mu) * inv + be;
            o.z = xv.z + (wv.z - mu) * inv + be;
            o.w = xv.w + (wv.w - mu) * inv + be;
            __stcs(&op[i], o);
        }
    }
}

// ---------------------------------------------------------------------------
// launch — single graph node.
// inputs: 0 x, 1 g_w, 2 g_b, 3 theta_w, 4 theta_b, 5 phi_w, 6 phi_b,
//         7 w_w, 8 w_b, 9 bn_gamma, 10 bn_beta
// ---------------------------------------------------------------------------
extern "C" void kernel_launch(void* const* d_in, const int* in_sizes, int n_in,
                              void* d_out, int out_size) {
    const float* x      = (const float*)d_in[0];
    const float* g_w    = (const float*)d_in[1];
    const float* g_b    = (const float*)d_in[2];
    const float* th_w   = (const float*)d_in[3];
    const float* th_b   = (const float*)d_in[4];
    const float* ph_w   = (const float*)d_in[5];
    const float* ph_b   = (const float*)d_in[6];
    const float* w_w    = (const float*)d_in[7];
    const float* w_b    = (const float*)d_in[8];
    const float* gamma  = (const float*)d_in[9];
    const float* beta   = (const float*)d_in[10];
    float* out          = (float*)d_out;

    fused_k<<<NBLK, NTHR>>>(x, g_w, g_b, th_w, th_b, ph_w, ph_b,
                            w_w, w_b, gamma, beta, out);
}